// round 3
// baseline (speedup 1.0000x reference)
#include <cuda_runtime.h>
#include <math.h>

#define Bsz   64
#define Tlen  512
#define Edim  512
#define Hdim  512
#define NCTA  128
#define TPB   256
// smem: Wa 32*512 + Wb 32*1024 + hbuf 8*1024 floats
#define SMEM_FLOATS (32*512 + 32*1024 + 8*1024)
#define SMEM_BYTES  (SMEM_FLOATS * 4)

__device__ float g_pre0[(size_t)Tlen * Bsz * Hdim];   // [t][b][h], 64 MB scratch
__device__ float g_h0[2][Bsz][Hdim];
__device__ float g_h1[2][Bsz][Hdim];
__device__ unsigned int g_bar_arrive;   // self-cleaning (always 0 after a full barrier)
__device__ unsigned int g_bar_gen;      // monotonically increasing; relative compare

// ---------------------------------------------------------------------------
// Zero initial hidden state (buffer 0 is the starting read buffer each launch)
// ---------------------------------------------------------------------------
__global__ void zero_h_kernel() {
    int i = blockIdx.x * blockDim.x + threadIdx.x;
    if (i < Bsz * Hdim) {
        ((float*)g_h0)[i] = 0.0f;   // g_h0[0][...]
        ((float*)g_h1)[i] = 0.0f;   // g_h1[0][...]
    }
}

// ---------------------------------------------------------------------------
// Precompute pre0[t][b][h] = emb[x[b,t]] . W_ih0[h] + b_ih0[h] + b_hh0[h]
// Tiled fp32 GEMM with row gather. Tile 64(m) x 64(n), K-chunks of 16,
// 256 threads, 4x4 register blocking (FMA/LDS.128 ratio = 8).
// m = t*64 + b  (all 64 rows of a block share the same t = blockIdx.x)
// ---------------------------------------------------------------------------
__global__ void __launch_bounds__(256) pre0_gemm_kernel(
    const int*   __restrict__ x,     // [64][512]
    const float* __restrict__ emb,   // [32000][512]
    const float* __restrict__ Wih,   // [2][512][512], layer 0 used here
    const float* __restrict__ bih,
    const float* __restrict__ bhh)
{
    __shared__ float As[16][64];
    __shared__ float Bs[16][64];
    __shared__ int   tok[64];

    const int tstep = blockIdx.x;          // 0..511
    const int ncol  = blockIdx.y * 64;     // 0..448
    const int tid   = threadIdx.x;

    if (tid < 64) tok[tid] = x[tid * Tlen + tstep];   // token for batch row = tid
    __syncthreads();

    const int ty = tid >> 4;   // 0..15
    const int tx = tid & 15;   // 0..15

    float acc[4][4];
#pragma unroll
    for (int i = 0; i < 4; i++)
#pragma unroll
        for (int j = 0; j < 4; j++) acc[i][j] = 0.0f;

    const int mm = tid & 63;
    const int kq = tid >> 6;   // 0..3

    for (int kc = 0; kc < Edim; kc += 16) {
        // load A tile (gathered embedding rows), transposed into As[k][m]
        {
            float4 v = *(const float4*)(emb + (size_t)tok[mm] * Edim + kc + kq * 4);
            As[kq*4+0][mm] = v.x; As[kq*4+1][mm] = v.y;
            As[kq*4+2][mm] = v.z; As[kq*4+3][mm] = v.w;
            float4 w = *(const float4*)(Wih + (size_t)(ncol + mm) * Edim + kc + kq * 4);
            Bs[kq*4+0][mm] = w.x; Bs[kq*4+1][mm] = w.y;
            Bs[kq*4+2][mm] = w.z; Bs[kq*4+3][mm] = w.w;
        }
        __syncthreads();
#pragma unroll
        for (int kk = 0; kk < 16; kk++) {
            float4 a = *(const float4*)(&As[kk][ty * 4]);
            float4 b = *(const float4*)(&Bs[kk][tx * 4]);
            acc[0][0] += a.x*b.x; acc[0][1] += a.x*b.y; acc[0][2] += a.x*b.z; acc[0][3] += a.x*b.w;
            acc[1][0] += a.y*b.x; acc[1][1] += a.y*b.y; acc[1][2] += a.y*b.z; acc[1][3] += a.y*b.w;
            acc[2][0] += a.z*b.x; acc[2][1] += a.z*b.y; acc[2][2] += a.z*b.z; acc[2][3] += a.z*b.w;
            acc[3][0] += a.w*b.x; acc[3][1] += a.w*b.y; acc[3][2] += a.w*b.z; acc[3][3] += a.w*b.w;
        }
        __syncthreads();
    }

    // epilogue: add biases (layer 0), store to g_pre0
    const int nbase = ncol + tx * 4;
    float4 bias;
    bias.x = bih[nbase + 0] + bhh[nbase + 0];
    bias.y = bih[nbase + 1] + bhh[nbase + 1];
    bias.z = bih[nbase + 2] + bhh[nbase + 2];
    bias.w = bih[nbase + 3] + bhh[nbase + 3];
#pragma unroll
    for (int i = 0; i < 4; i++) {
        const int m = tstep * 64 + ty * 4 + i;     // = t*B + b
        float4 o;
        o.x = acc[i][0] + bias.x; o.y = acc[i][1] + bias.y;
        o.z = acc[i][2] + bias.z; o.w = acc[i][3] + bias.w;
        *(float4*)(g_pre0 + (size_t)m * Hdim + nbase) = o;
    }
}

// ---------------------------------------------------------------------------
// Software grid barrier (all 128 CTAs wave-1 resident: 224KB smem -> 1 CTA/SM)
// ---------------------------------------------------------------------------
__device__ __forceinline__ void grid_barrier() {
    __threadfence();
    __syncthreads();
    if (threadIdx.x == 0) {
        unsigned int my = *(volatile unsigned int*)&g_bar_gen;
        unsigned int prev = atomicAdd(&g_bar_arrive, 1u);
        if (prev == (unsigned)(NCTA - 1)) {
            atomicExch(&g_bar_arrive, 0u);
            __threadfence();
            atomicAdd(&g_bar_gen, 1u);
        } else {
            while (*(volatile unsigned int*)&g_bar_gen == my) { __nanosleep(32); }
        }
        __threadfence();
    }
    __syncthreads();
}

// Per-thread tile GEMM phase: 4x4 outputs, K-sliced 16 ways, float4 LDS.
// hbuf rows have stride 1024 floats; W rows have stride WSTRIDE floats.
template<int JCOUNT, int WSTRIDE>
__device__ __forceinline__ void phase_accum(
    const float* __restrict__ hbuf, const float* __restrict__ W,
    int tb, int th, int ks, float acc[4][4])
{
#pragma unroll
    for (int bi = 0; bi < 4; bi++)
#pragma unroll
        for (int hi = 0; hi < 4; hi++) acc[bi][hi] = 0.0f;

#pragma unroll 4
    for (int j = 0; j < JCOUNT; j++) {
        const int k = ((j * 16 + ks) << 2);
        float4 a[4], w[4];
#pragma unroll
        for (int q = 0; q < 4; q++) a[q] = *(const float4*)(hbuf + (size_t)(tb + q) * 1024 + k);
#pragma unroll
        for (int q = 0; q < 4; q++) w[q] = *(const float4*)(W + (size_t)(th + q) * WSTRIDE + k);
#pragma unroll
        for (int bi = 0; bi < 4; bi++)
#pragma unroll
            for (int hi = 0; hi < 4; hi++) {
                acc[bi][hi] += a[bi].x * w[hi].x;
                acc[bi][hi] += a[bi].y * w[hi].y;
                acc[bi][hi] += a[bi].z * w[hi].z;
                acc[bi][hi] += a[bi].w * w[hi].w;
            }
    }
}

// ---------------------------------------------------------------------------
// Persistent sequential RNN kernel. 128 CTAs, 256 threads.
// CTA tile: 8 batches x 32 h-outputs. Weights resident in smem all 512 steps.
// ---------------------------------------------------------------------------
__global__ void __launch_bounds__(TPB, 1) rnn_seq_kernel(
    const float* __restrict__ Wih,   // [2][512][512]
    const float* __restrict__ Whh,   // [2][512][512]
    const float* __restrict__ bih,   // [2][512]
    const float* __restrict__ bhh,   // [2][512]
    const int*   __restrict__ lengths,
    float*       __restrict__ out)
{
    extern __shared__ float smem_dyn[];
    float* Wa   = smem_dyn;                 // 32 x 512  (W_hh0 slice)
    float* Wb   = smem_dyn + 32 * 512;      // 32 x 1024 ([W_ih1 | W_hh1] slice)
    float* hbuf = Wb + 32 * 1024;           // 8 x 1024  (h staging; aliased as red buf)

    const int cta   = blockIdx.x;
    const int bbase = (cta >> 4) * 8;       // 8 batch-blocks
    const int hbase = (cta & 15) * 32;      // 16 h-blocks
    const int tid   = threadIdx.x;

    // --- load resident weight slices into smem ---
    {
        const float4* src = (const float4*)(Whh + (size_t)hbase * Hdim);
        float4* dst = (float4*)Wa;
        for (int i = tid; i < 32 * Hdim / 4; i += TPB) dst[i] = src[i];

        const float4* s1 = (const float4*)(Wih + (size_t)Hdim * Edim + (size_t)hbase * Edim);
        const float4* s2 = (const float4*)(Whh + (size_t)Hdim * Hdim + (size_t)hbase * Hdim);
        for (int i = tid; i < 32 * 512 / 4; i += TPB) {
            int r = i >> 7, c = i & 127;
            ((float4*)(Wb + (size_t)r * 1024))[c]       = s1[i];
            ((float4*)(Wb + (size_t)r * 1024 + 512))[c] = s2[i];
        }
    }

    // finalize mapping: thread tid handles output (bl, hl)
    const int bl = tid >> 5, hl = tid & 31;
    const int b_g = bbase + bl, h_g = hbase + hl;
    const float b1s = bih[Hdim + h_g] + bhh[Hdim + h_g];
    const int len_b = lengths[b_g];
    const int redidx = ((((bl >> 2) * 8 + (hl >> 2)) * 16) + ((bl & 3) * 4 + (hl & 3))) * 20;

    // compute mapping: ks = k-slice, g = output group (2 b-groups x 8 h-groups)
    const int ks = tid & 15;
    const int g  = tid >> 4;
    const int tb = (g >> 3) * 4;
    const int th = (g & 7) * 4;

    int p = 0;
    for (int step = 0; step < Tlen; ++step) {
        // ================= Phase A: h0_new = tanh(pre0 + h0 @ Whh0^T) ========
        __syncthreads();
        for (int i = tid; i < 8 * 512 / 4; i += TPB) {
            int r = i >> 7, c = i & 127;
            ((float4*)(hbuf + (size_t)r * 1024))[c] =
                ((const float4*)(&g_h0[p][bbase + r][0]))[c];
        }
        __syncthreads();

        float acc[4][4];
        phase_accum<8, 512>(hbuf, Wa, tb, th, ks, acc);

        __syncthreads();
        {   // reduction staging (aliases hbuf; stride 20 to spread banks)
            float* red = hbuf;
#pragma unroll
            for (int bi = 0; bi < 4; bi++)
#pragma unroll
                for (int hi = 0; hi < 4; hi++)
                    red[(g * 16 + bi * 4 + hi) * 20 + ks] = acc[bi][hi];
        }
        __syncthreads();
        {
            float s = 0.0f;
            const float* rp = hbuf + redidx;
#pragma unroll
            for (int i = 0; i < 16; i += 4) {
                float4 v = *(const float4*)(rp + i);
                s += (v.x + v.y) + (v.z + v.w);
            }
            s += g_pre0[((size_t)step * Bsz + b_g) * Hdim + h_g];
            float hprev = g_h0[p][b_g][h_g];
            float hnew = (step < len_b) ? tanhf(s) : hprev;
            g_h0[p ^ 1][b_g][h_g] = hnew;
        }
        grid_barrier();

        // ====== Phase B: h1_new = tanh([h0_new,h1] @ [Wih1|Whh1]^T + b1) =====
        for (int i = tid; i < 8 * 512 / 4; i += TPB) {
            int r = i >> 7, c = i & 127;
            ((float4*)(hbuf + (size_t)r * 1024))[c] =
                ((const float4*)(&g_h0[p ^ 1][bbase + r][0]))[c];
            ((float4*)(hbuf + (size_t)r * 1024 + 512))[c] =
                ((const float4*)(&g_h1[p][bbase + r][0]))[c];
        }
        __syncthreads();

        phase_accum<16, 1024>(hbuf, Wb, tb, th, ks, acc);

        __syncthreads();
        {
            float* red = hbuf;
#pragma unroll
            for (int bi = 0; bi < 4; bi++)
#pragma unroll
                for (int hi = 0; hi < 4; hi++)
                    red[(g * 16 + bi * 4 + hi) * 20 + ks] = acc[bi][hi];
        }
        __syncthreads();
        {
            float s = b1s;
            const float* rp = hbuf + redidx;
#pragma unroll
            for (int i = 0; i < 16; i += 4) {
                float4 v = *(const float4*)(rp + i);
                s += (v.x + v.y) + (v.z + v.w);
            }
            float hprev = g_h1[p][b_g][h_g];
            float hnew = (step < len_b) ? tanhf(s) : hprev;
            g_h1[p ^ 1][b_g][h_g] = hnew;
        }
        grid_barrier();
        p ^= 1;
    }

    // ===== outputs: [ h1_final (64x512) | hidden (64x2x512) ] =====
    // After 512 steps p==0 and final state lives in buffer 0.
    {
        float h0f = g_h0[0][b_g][h_g];
        float h1f = g_h1[0][b_g][h_g];
        out[(size_t)b_g * Hdim + h_g] = h1f;
        out[(size_t)Bsz * Hdim + (size_t)b_g * 2 * Hdim + h_g] = h0f;
        out[(size_t)Bsz * Hdim + (size_t)b_g * 2 * Hdim + Hdim + h_g] = h1f;
    }
}

// ---------------------------------------------------------------------------
extern "C" void kernel_launch(void* const* d_in, const int* in_sizes, int n_in,
                              void* d_out, int out_size) {
    const int*   x       = (const int*)  d_in[0];
    const int*   lengths = (const int*)  d_in[1];
    const float* emb     = (const float*)d_in[2];
    const float* Wih     = (const float*)d_in[3];
    const float* Whh     = (const float*)d_in[4];
    const float* bih     = (const float*)d_in[5];
    const float* bhh     = (const float*)d_in[6];
    float* out = (float*)d_out;

    cudaFuncSetAttribute(rnn_seq_kernel,
                         cudaFuncAttributeMaxDynamicSharedMemorySize, SMEM_BYTES);

    zero_h_kernel<<<(Bsz * Hdim + 255) / 256, 256>>>();

    dim3 grid_pre(Tlen, Hdim / 64);   // (512, 8)
    pre0_gemm_kernel<<<grid_pre, 256>>>(x, emb, Wih, bih, bhh);

    rnn_seq_kernel<<<NCTA, TPB, SMEM_BYTES>>>(Wih, Whh, bih, bhh, lengths, out);
}

// round 4
// speedup vs baseline: 1.2461x; 1.2461x over previous
#include <cuda_runtime.h>
#include <math.h>

#define Bsz   64
#define Tlen  512
#define Edim  512
#define Hdim  512
#define NCTA  128
#define TPB   256
// smem: Wa 32*512 + Wb 32*1024 + hbuf 8*1024 floats = 229376 bytes
#define SMEM_FLOATS (32*512 + 32*1024 + 8*1024)
#define SMEM_BYTES  (SMEM_FLOATS * 4)

__device__ float g_pre0[(size_t)Tlen * Bsz * Hdim];   // [t][b][h], 64 MB scratch
__device__ float g_h0[2][Bsz][Hdim];
__device__ float g_h1[2][Bsz][Hdim];
// 2-level barrier state (self-cleaning: counters return to 0; gen monotonic)
__device__ unsigned int g_grp[16 * 32];   // group counters, 128B apart
__device__ unsigned int g_root;
__device__ unsigned int g_gen;

// ---------------------------------------------------------------------------
// acquire/release primitives (gpu scope)
// ---------------------------------------------------------------------------
__device__ __forceinline__ unsigned atom_add_release_gpu(unsigned* p, unsigned v) {
    unsigned old;
    asm volatile("atom.add.release.gpu.u32 %0, [%1], %2;"
                 : "=r"(old) : "l"(p), "r"(v) : "memory");
    return old;
}
__device__ __forceinline__ unsigned ld_acquire_gpu(const unsigned* p) {
    unsigned v;
    asm volatile("ld.acquire.gpu.u32 %0, [%1];" : "=r"(v) : "l"(p) : "memory");
    return v;
}
__device__ __forceinline__ void st_relaxed_gpu(unsigned* p, unsigned v) {
    asm volatile("st.relaxed.gpu.u32 [%0], %1;" :: "l"(p), "r"(v) : "memory");
}

// ---------------------------------------------------------------------------
// Zero initial hidden state (both parity buffers of both layers)
// ---------------------------------------------------------------------------
__global__ void zero_h_kernel() {
    int i = blockIdx.x * blockDim.x + threadIdx.x;
    if (i < 2 * Bsz * Hdim) {
        ((float*)g_h0)[i] = 0.0f;
        ((float*)g_h1)[i] = 0.0f;
    }
}

// ---------------------------------------------------------------------------
// Precompute pre0[t][b][h] = emb[x[b,t]] . W_ih0[h] + b_ih0[h] + b_hh0[h]
// (unchanged from R2 — FMA-bound ~0.5 ms)
// ---------------------------------------------------------------------------
__global__ void __launch_bounds__(256) pre0_gemm_kernel(
    const int*   __restrict__ x,
    const float* __restrict__ emb,
    const float* __restrict__ Wih,
    const float* __restrict__ bih,
    const float* __restrict__ bhh)
{
    __shared__ float As[16][64];
    __shared__ float Bs[16][64];
    __shared__ int   tok[64];

    const int tstep = blockIdx.x;
    const int ncol  = blockIdx.y * 64;
    const int tid   = threadIdx.x;

    if (tid < 64) tok[tid] = x[tid * Tlen + tstep];
    __syncthreads();

    const int ty = tid >> 4;
    const int tx = tid & 15;

    float acc[4][4];
#pragma unroll
    for (int i = 0; i < 4; i++)
#pragma unroll
        for (int j = 0; j < 4; j++) acc[i][j] = 0.0f;

    const int mm = tid & 63;
    const int kq = tid >> 6;

    for (int kc = 0; kc < Edim; kc += 16) {
        {
            float4 v = *(const float4*)(emb + (size_t)tok[mm] * Edim + kc + kq * 4);
            As[kq*4+0][mm] = v.x; As[kq*4+1][mm] = v.y;
            As[kq*4+2][mm] = v.z; As[kq*4+3][mm] = v.w;
            float4 w = *(const float4*)(Wih + (size_t)(ncol + mm) * Edim + kc + kq * 4);
            Bs[kq*4+0][mm] = w.x; Bs[kq*4+1][mm] = w.y;
            Bs[kq*4+2][mm] = w.z; Bs[kq*4+3][mm] = w.w;
        }
        __syncthreads();
#pragma unroll
        for (int kk = 0; kk < 16; kk++) {
            float4 a = *(const float4*)(&As[kk][ty * 4]);
            float4 b = *(const float4*)(&Bs[kk][tx * 4]);
            acc[0][0] += a.x*b.x; acc[0][1] += a.x*b.y; acc[0][2] += a.x*b.z; acc[0][3] += a.x*b.w;
            acc[1][0] += a.y*b.x; acc[1][1] += a.y*b.y; acc[1][2] += a.y*b.z; acc[1][3] += a.y*b.w;
            acc[2][0] += a.z*b.x; acc[2][1] += a.z*b.y; acc[2][2] += a.z*b.z; acc[2][3] += a.z*b.w;
            acc[3][0] += a.w*b.x; acc[3][1] += a.w*b.y; acc[3][2] += a.w*b.z; acc[3][3] += a.w*b.w;
        }
        __syncthreads();
    }

    const int nbase = ncol + tx * 4;
    float4 bias;
    bias.x = bih[nbase + 0] + bhh[nbase + 0];
    bias.y = bih[nbase + 1] + bhh[nbase + 1];
    bias.z = bih[nbase + 2] + bhh[nbase + 2];
    bias.w = bih[nbase + 3] + bhh[nbase + 3];
#pragma unroll
    for (int i = 0; i < 4; i++) {
        const int m = tstep * 64 + ty * 4 + i;
        float4 o;
        o.x = acc[i][0] + bias.x; o.y = acc[i][1] + bias.y;
        o.z = acc[i][2] + bias.z; o.w = acc[i][3] + bias.w;
        *(float4*)(g_pre0 + (size_t)m * Hdim + nbase) = o;
    }
}

// ---------------------------------------------------------------------------
// 2-level grid barrier: 16 groups of 8 CTAs -> root of 16 -> gen increment.
// No L1 flush: release orders writes to L2; readers use __ldcg / acquire.
// ---------------------------------------------------------------------------
__device__ __forceinline__ void grid_barrier(unsigned &target) {
    __syncthreads();
    if (threadIdx.x == 0) {
        target += 1;
        const int grp = blockIdx.x >> 3;                 // 16 groups of 8
        unsigned prev = atom_add_release_gpu(&g_grp[grp * 32], 1u);
        if (prev == 7u) {
            st_relaxed_gpu(&g_grp[grp * 32], 0u);
            unsigned p2 = atom_add_release_gpu(&g_root, 1u);
            if (p2 == 15u) {
                st_relaxed_gpu(&g_root, 0u);
                atom_add_release_gpu(&g_gen, 1u);
            }
        }
        while ((int)(ld_acquire_gpu(&g_gen) - target) < 0) { }
    }
    __syncthreads();
}

// Per-thread tile GEMM: 4x4 outputs, K-sliced 16 ways, float4 LDS.
template<int JCOUNT, int WSTRIDE>
__device__ __forceinline__ void phase_accum(
    const float* __restrict__ hbuf, const float* __restrict__ W,
    int tb, int th, int ks, float acc[4][4])
{
#pragma unroll
    for (int bi = 0; bi < 4; bi++)
#pragma unroll
        for (int hi = 0; hi < 4; hi++) acc[bi][hi] = 0.0f;

#pragma unroll 4
    for (int j = 0; j < JCOUNT; j++) {
        const int k = ((j * 16 + ks) << 2);
        float4 a[4], w[4];
#pragma unroll
        for (int q = 0; q < 4; q++) a[q] = *(const float4*)(hbuf + (size_t)(tb + q) * 1024 + k);
#pragma unroll
        for (int q = 0; q < 4; q++) w[q] = *(const float4*)(W + (size_t)(th + q) * WSTRIDE + k);
#pragma unroll
        for (int bi = 0; bi < 4; bi++)
#pragma unroll
            for (int hi = 0; hi < 4; hi++) {
                acc[bi][hi] += a[bi].x * w[hi].x;
                acc[bi][hi] += a[bi].y * w[hi].y;
                acc[bi][hi] += a[bi].z * w[hi].z;
                acc[bi][hi] += a[bi].w * w[hi].w;
            }
    }
}

// ---------------------------------------------------------------------------
// Persistent pipelined RNN kernel. 128 CTAs, 256 threads, ONE barrier/phase.
// Phase s: computes h0_after[s] (s<512) and h1_after[s-1] (s>=1).
// Both consume h0_after[s-1], h1_after[s-2] staged once into smem.
// ---------------------------------------------------------------------------
__global__ void __launch_bounds__(TPB, 1) rnn_seq_kernel(
    const float* __restrict__ Wih,
    const float* __restrict__ Whh,
    const float* __restrict__ bih,
    const float* __restrict__ bhh,
    const int*   __restrict__ lengths,
    float*       __restrict__ out)
{
    extern __shared__ float smem_dyn[];
    float* Wa   = smem_dyn;                 // 32 x 512  (W_hh0 slice)
    float* Wb   = smem_dyn + 32 * 512;      // 32 x 1024 ([W_ih1 | W_hh1] slice)
    float* hbuf = Wb + 32 * 1024;           // 8 x 1024  (h staging; aliased as red buf)

    const int cta   = blockIdx.x;
    const int bbase = (cta >> 4) * 8;
    const int hbase = (cta & 15) * 32;
    const int tid   = threadIdx.x;

    // resident weight slices
    {
        const float4* src = (const float4*)(Whh + (size_t)hbase * Hdim);
        float4* dst = (float4*)Wa;
        for (int i = tid; i < 32 * Hdim / 4; i += TPB) dst[i] = src[i];

        const float4* s1 = (const float4*)(Wih + (size_t)Hdim * Edim + (size_t)hbase * Edim);
        const float4* s2 = (const float4*)(Whh + (size_t)Hdim * Hdim + (size_t)hbase * Hdim);
        for (int i = tid; i < 32 * 512 / 4; i += TPB) {
            int r = i >> 7, c = i & 127;
            ((float4*)(Wb + (size_t)r * 1024))[c]       = s1[i];
            ((float4*)(Wb + (size_t)r * 1024 + 512))[c] = s2[i];
        }
    }

    // output-ownership mapping
    const int bl = tid >> 5, hl = tid & 31;
    const int b_g = bbase + bl, h_g = hbase + hl;
    const float b1s = bih[Hdim + h_g] + bhh[Hdim + h_g];
    const int len_b = lengths[b_g];
    const int redidx = ((((bl >> 2) * 8 + (hl >> 2)) * 16) + ((bl & 3) * 4 + (hl & 3))) * 20;

    // compute mapping
    const int ks = tid & 15;
    const int g  = tid >> 4;
    const int tb = (g >> 3) * 4;
    const int th = (g & 7) * 4;

    unsigned target = 0;
    if (tid == 0) target = ld_acquire_gpu(&g_gen);

    float h0fin = 0.0f, h1fin = 0.0f;

    for (int s = 0; s <= Tlen; ++s) {
        const int p = s & 1;

        // ---- stage h0_after[s-1], h1_after[s-2] (L2-coherent reads) ----
        __syncthreads();   // previous phase's red reads are done (barrier covers it for s>0)
        for (int i = tid; i < 1024; i += TPB) {
            int r = i >> 7, c = (i & 127) << 2;
            float4 v0 = __ldcg((const float4*)&g_h0[p][bbase + r][c]);
            float4 v1 = __ldcg((const float4*)&g_h1[p][bbase + r][c]);
            *(float4*)(hbuf + (size_t)r * 1024 + c)       = v0;
            *(float4*)(hbuf + (size_t)r * 1024 + 512 + c) = v1;
        }
        __syncthreads();

        const float hprev0 = hbuf[(size_t)bl * 1024 + h_g];
        const float hprev1 = hbuf[(size_t)bl * 1024 + 512 + h_g];

        float acc0[4][4], acc1[4][4];
        if (s < Tlen) phase_accum<8, 512>(hbuf, Wa, tb, th, ks, acc0);
        if (s >= 1)   phase_accum<16, 1024>(hbuf, Wb, tb, th, ks, acc1);

        // ---- layer-0 reduction (red buf aliases hbuf) ----
        __syncthreads();
        if (s < Tlen) {
#pragma unroll
            for (int bi = 0; bi < 4; bi++)
#pragma unroll
                for (int hi = 0; hi < 4; hi++)
                    hbuf[(g * 16 + bi * 4 + hi) * 20 + ks] = acc0[bi][hi];
        }
        __syncthreads();
        if (s < Tlen) {
            float sum = 0.0f;
            const float* rp = hbuf + redidx;
#pragma unroll
            for (int i = 0; i < 16; i += 4) {
                float4 v = *(const float4*)(rp + i);
                sum += (v.x + v.y) + (v.z + v.w);
            }
            sum += g_pre0[((size_t)s * Bsz + b_g) * Hdim + h_g];
            float hnew0 = (s < len_b) ? tanhf(sum) : hprev0;
            g_h0[p ^ 1][b_g][h_g] = hnew0;
            if (s == Tlen - 1) h0fin = hnew0;
        }

        // ---- layer-1 reduction ----
        __syncthreads();
        if (s >= 1) {
#pragma unroll
            for (int bi = 0; bi < 4; bi++)
#pragma unroll
                for (int hi = 0; hi < 4; hi++)
                    hbuf[(g * 16 + bi * 4 + hi) * 20 + ks] = acc1[bi][hi];
        }
        __syncthreads();
        if (s >= 1) {
            float sum = b1s;
            const float* rp = hbuf + redidx;
#pragma unroll
            for (int i = 0; i < 16; i += 4) {
                float4 v = *(const float4*)(rp + i);
                sum += (v.x + v.y) + (v.z + v.w);
            }
            float hnew1 = ((s - 1) < len_b) ? tanhf(sum) : hprev1;
            if (s < Tlen) g_h1[p ^ 1][b_g][h_g] = hnew1;
            else          h1fin = hnew1;     // final: nobody reads it, keep in reg
        }

        if (s < Tlen) grid_barrier(target);   // single barrier per phase
    }

    // outputs: [ h1_final (64x512) | hidden (64x2x512: layer0, layer1) ]
    out[(size_t)b_g * Hdim + h_g] = h1fin;
    out[(size_t)Bsz * Hdim + (size_t)b_g * 2 * Hdim + h_g] = h0fin;
    out[(size_t)Bsz * Hdim + (size_t)b_g * 2 * Hdim + Hdim + h_g] = h1fin;
}

// ---------------------------------------------------------------------------
extern "C" void kernel_launch(void* const* d_in, const int* in_sizes, int n_in,
                              void* d_out, int out_size) {
    const int*   x       = (const int*)  d_in[0];
    const int*   lengths = (const int*)  d_in[1];
    const float* emb     = (const float*)d_in[2];
    const float* Wih     = (const float*)d_in[3];
    const float* Whh     = (const float*)d_in[4];
    const float* bih     = (const float*)d_in[5];
    const float* bhh     = (const float*)d_in[6];
    float* out = (float*)d_out;

    cudaFuncSetAttribute(rnn_seq_kernel,
                         cudaFuncAttributeMaxDynamicSharedMemorySize, SMEM_BYTES);

    zero_h_kernel<<<(2 * Bsz * Hdim + 255) / 256, 256>>>();

    dim3 grid_pre(Tlen, Hdim / 64);
    pre0_gemm_kernel<<<grid_pre, 256>>>(x, emb, Wih, bih, bhh);

    rnn_seq_kernel<<<NCTA, TPB, SMEM_BYTES>>>(Wih, Whh, bih, bhh, lengths, out);
}

// round 5
// speedup vs baseline: 1.6753x; 1.3444x over previous
#include <cuda_runtime.h>
#include <math.h>

#define Bsz   64
#define Tlen  512
#define Edim  512
#define Hdim  512
#define NCTA  128
#define TPB   256
// smem: Wa 32*512 + Wb 32*1024 + hbuf 8*1024 floats = 224 KB
#define SMEM_FLOATS (32*512 + 32*1024 + 8*1024)
#define SMEM_BYTES  (SMEM_FLOATS * 4)

__device__ float g_pre0[(size_t)Tlen * Bsz * Hdim];   // [t][b][h]
__device__ float g_h0[2][Bsz][Hdim];
__device__ float g_h1[2][Bsz][Hdim];
// per-group barrier state (8 groups of 16 CTAs), 128B padding
__device__ unsigned int g_garr[8 * 32];
__device__ unsigned int g_ggen[8 * 32];

// ---------------------------------------------------------------------------
// primitives
// ---------------------------------------------------------------------------
__device__ __forceinline__ unsigned atom_add_acq_rel_gpu(unsigned* p, unsigned v) {
    unsigned old;
    asm volatile("atom.add.acq_rel.gpu.u32 %0, [%1], %2;"
                 : "=r"(old) : "l"(p), "r"(v) : "memory");
    return old;
}
__device__ __forceinline__ unsigned atom_add_release_gpu(unsigned* p, unsigned v) {
    unsigned old;
    asm volatile("atom.add.release.gpu.u32 %0, [%1], %2;"
                 : "=r"(old) : "l"(p), "r"(v) : "memory");
    return old;
}
__device__ __forceinline__ unsigned ld_acquire_gpu(const unsigned* p) {
    unsigned v;
    asm volatile("ld.acquire.gpu.u32 %0, [%1];" : "=r"(v) : "l"(p) : "memory");
    return v;
}
__device__ __forceinline__ void st_relaxed_gpu(unsigned* p, unsigned v) {
    asm volatile("st.relaxed.gpu.u32 [%0], %1;" :: "l"(p), "r"(v) : "memory");
}
// packed fp32x2 FMA: d.lo += a.lo*b.lo ; d.hi += a.hi*b.hi (bitwise = 2x FFMA)
__device__ __forceinline__ void F2(unsigned long long &d, unsigned long long a,
                                   unsigned long long b) {
    asm("fma.rn.f32x2 %0, %1, %2, %0;" : "+l"(d) : "l"(a), "l"(b));
}
__device__ __forceinline__ unsigned long long pk2(float x, float y) {
    unsigned long long p;
    asm("mov.b64 %0, {%1, %2};" : "=l"(p) : "f"(x), "f"(y));
    return p;
}
__device__ __forceinline__ float2 upk(unsigned long long v) {
    float2 r;
    asm("mov.b64 {%0, %1}, %2;" : "=f"(r.x), "=f"(r.y) : "l"(v));
    return r;
}

// ---------------------------------------------------------------------------
__global__ void zero_h_kernel() {
    int i = blockIdx.x * blockDim.x + threadIdx.x;
    if (i < 2 * Bsz * Hdim) {
        ((float*)g_h0)[i] = 0.0f;
        ((float*)g_h1)[i] = 0.0f;
    }
}

// ---------------------------------------------------------------------------
// pre0[t][b][h] = emb[x[b,t]] . W_ih0[h] + b_ih0[h] + b_hh0[h]
// f32x2 inner product; smem holds k-PAIRS (ull) with a bank swizzle:
// phys column = m ^ (((m>>4)&1)<<1)  (permutes 16B chunks; conflict-free reads)
// ---------------------------------------------------------------------------
__global__ void __launch_bounds__(256) pre0_gemm_kernel(
    const int*   __restrict__ x,
    const float* __restrict__ emb,
    const float* __restrict__ Wih,
    const float* __restrict__ bih,
    const float* __restrict__ bhh)
{
    __shared__ unsigned long long As2[8][64];   // [k-pair][m]
    __shared__ unsigned long long Bs2[8][64];   // [k-pair][n]
    __shared__ int tok[64];

    const int tstep = blockIdx.x;
    const int ncol  = blockIdx.y * 64;
    const int tid   = threadIdx.x;

    if (tid < 64) tok[tid] = x[tid * Tlen + tstep];
    __syncthreads();

    const int ty = tid >> 4;
    const int tx = tid & 15;
    const int mm = tid & 63;
    const int kq = tid >> 6;
    const int pm = mm ^ (((mm >> 4) & 1) << 1);           // swizzled write col

    const int xa  = ((ty >> 2) & 1) << 1;
    const int xb  = ((tx >> 2) & 1) << 1;
    const int ca0 = (ty * 4) ^ xa, ca2 = (ty * 4 + 2) ^ xa;
    const int cb0 = (tx * 4) ^ xb, cb2 = (tx * 4 + 2) ^ xb;

    unsigned long long acc2[4][4];
#pragma unroll
    for (int i = 0; i < 4; i++)
#pragma unroll
        for (int j = 0; j < 4; j++) acc2[i][j] = 0ull;

    for (int kc = 0; kc < Edim; kc += 16) {
        {
            float4 v = *(const float4*)(emb + (size_t)tok[mm] * Edim + kc + kq * 4);
            As2[kq*2+0][pm] = pk2(v.x, v.y);
            As2[kq*2+1][pm] = pk2(v.z, v.w);
            float4 w = *(const float4*)(Wih + (size_t)(ncol + mm) * Edim + kc + kq * 4);
            Bs2[kq*2+0][pm] = pk2(w.x, w.y);
            Bs2[kq*2+1][pm] = pk2(w.z, w.w);
        }
        __syncthreads();
#pragma unroll
        for (int kk2 = 0; kk2 < 8; kk2++) {
            ulonglong2 a01 = *(const ulonglong2*)&As2[kk2][ca0];
            ulonglong2 a23 = *(const ulonglong2*)&As2[kk2][ca2];
            ulonglong2 b01 = *(const ulonglong2*)&Bs2[kk2][cb0];
            ulonglong2 b23 = *(const ulonglong2*)&Bs2[kk2][cb2];
            unsigned long long am[4] = {a01.x, a01.y, a23.x, a23.y};
            unsigned long long bn[4] = {b01.x, b01.y, b23.x, b23.y};
#pragma unroll
            for (int i = 0; i < 4; i++)
#pragma unroll
                for (int j = 0; j < 4; j++) F2(acc2[i][j], am[i], bn[j]);
        }
        __syncthreads();
    }

    const int nbase = ncol + tx * 4;
    float4 bias;
    bias.x = bih[nbase + 0] + bhh[nbase + 0];
    bias.y = bih[nbase + 1] + bhh[nbase + 1];
    bias.z = bih[nbase + 2] + bhh[nbase + 2];
    bias.w = bih[nbase + 3] + bhh[nbase + 3];
#pragma unroll
    for (int i = 0; i < 4; i++) {
        const int m = tstep * 64 + ty * 4 + i;
        float2 u0 = upk(acc2[i][0]), u1 = upk(acc2[i][1]);
        float2 u2 = upk(acc2[i][2]), u3 = upk(acc2[i][3]);
        float4 o;
        o.x = u0.x + u0.y + bias.x;  o.y = u1.x + u1.y + bias.y;
        o.z = u2.x + u2.y + bias.z;  o.w = u3.x + u3.y + bias.w;
        *(float4*)(g_pre0 + (size_t)m * Hdim + nbase) = o;
    }
}

// ---------------------------------------------------------------------------
// Per-group barrier (16 CTAs sharing one bbase). Single-level acq_rel.
// ---------------------------------------------------------------------------
__device__ __forceinline__ void group_barrier(int grp, unsigned &target) {
    __syncthreads();
    if (threadIdx.x == 0) {
        target += 1;
        unsigned prev = atom_add_acq_rel_gpu(&g_garr[grp * 32], 1u);
        if (prev == 15u) {
            st_relaxed_gpu(&g_garr[grp * 32], 0u);
            atom_add_release_gpu(&g_ggen[grp * 32], 1u);
        }
        while ((int)(ld_acquire_gpu(&g_ggen[grp * 32]) - target) < 0) { }
    }
    __syncthreads();
}

// f32x2 GEMM phase: 4x4 outputs, K-sliced 16 ways (k contiguous -> free packing)
template<int JCOUNT, int WSTRIDE>
__device__ __forceinline__ void phase_accum2(
    const float* __restrict__ hbuf, const float* __restrict__ W,
    int tb, int th, int ks, unsigned long long acc[4][4])
{
#pragma unroll
    for (int bi = 0; bi < 4; bi++)
#pragma unroll
        for (int hi = 0; hi < 4; hi++) acc[bi][hi] = 0ull;

#pragma unroll 4
    for (int j = 0; j < JCOUNT; j++) {
        const int k = ((j * 16 + ks) << 2);
        ulonglong2 a[4], w[4];
#pragma unroll
        for (int q = 0; q < 4; q++)
            a[q] = *(const ulonglong2*)(hbuf + (size_t)(tb + q) * 1024 + k);
#pragma unroll
        for (int q = 0; q < 4; q++)
            w[q] = *(const ulonglong2*)(W + (size_t)(th + q) * WSTRIDE + k);
#pragma unroll
        for (int bi = 0; bi < 4; bi++)
#pragma unroll
            for (int hi = 0; hi < 4; hi++) {
                F2(acc[bi][hi], a[bi].x, w[hi].x);
                F2(acc[bi][hi], a[bi].y, w[hi].y);
            }
    }
}

// In-register cross-k-split reduction over the 16-lane segment.
// Input: v[i] = partial of tile-output i (this lane's k-slice).
// Output: lane k (within segment) holds full sum of output k in v[0].
__device__ __forceinline__ void fold16(float v[16], int ks) {
#pragma unroll
    for (int m = 8; m >= 1; m >>= 1) {
        const bool hi = (ks & m) != 0;
#pragma unroll
        for (int j = 0; j < m; j++) {
            float send = hi ? v[j] : v[j + m];
            float recv = __shfl_xor_sync(0xffffffffu, send, m, 16);
            float keep = hi ? v[j + m] : v[j];
            v[j] = keep + recv;
        }
    }
}

// ---------------------------------------------------------------------------
// Persistent pipelined RNN. 128 CTAs = 8 independent groups of 16.
// Phase s: h0_after[s] (s<512) and h1_after[s-1] (s>=1); 1 barrier/phase.
// ---------------------------------------------------------------------------
__global__ void __launch_bounds__(TPB, 1) rnn_seq_kernel(
    const float* __restrict__ Wih,
    const float* __restrict__ Whh,
    const float* __restrict__ bih,
    const float* __restrict__ bhh,
    const int*   __restrict__ lengths,
    float*       __restrict__ out)
{
    extern __shared__ float smem_dyn[];
    float* Wa   = smem_dyn;                 // 32 x 512
    float* Wb   = smem_dyn + 32 * 512;      // 32 x 1024
    float* hbuf = Wb + 32 * 1024;           // 8 x 1024 staging

    const int cta   = blockIdx.x;
    const int grp   = cta >> 4;             // 8 batch groups
    const int bbase = grp * 8;
    const int hbase = (cta & 15) * 32;
    const int tid   = threadIdx.x;

    // resident weight slices
    {
        const float4* src = (const float4*)(Whh + (size_t)hbase * Hdim);
        float4* dst = (float4*)Wa;
        for (int i = tid; i < 32 * Hdim / 4; i += TPB) dst[i] = src[i];

        const float4* s1 = (const float4*)(Wih + (size_t)Hdim * Edim + (size_t)hbase * Edim);
        const float4* s2 = (const float4*)(Whh + (size_t)Hdim * Hdim + (size_t)hbase * Hdim);
        for (int i = tid; i < 32 * 512 / 4; i += TPB) {
            int r = i >> 7, c = i & 127;
            ((float4*)(Wb + (size_t)r * 1024))[c]       = s1[i];
            ((float4*)(Wb + (size_t)r * 1024 + 512))[c] = s2[i];
        }
    }

    // compute mapping (warp halves share tb -> a-stream broadcast)
    const int ks = tid & 15;
    const int g  = tid >> 4;
    const int tb = (g >> 3) * 4;
    const int th = (g & 7) * 4;

    // epilogue ownership: lane ks of group g owns tile-output index ks
    const int blo = tb + (ks >> 2);          // 0..7
    const int hlo = th + (ks & 3);           // 0..31
    const int b_o = bbase + blo;
    const int h_o = hbase + hlo;
    const int lenb = lengths[b_o];
    const float bias1 = bih[Hdim + h_o] + bhh[Hdim + h_o];

    // group horizon: frozen beyond max length in the group
    int smax = 1;
#pragma unroll
    for (int q = 0; q < 8; q++) {
        int l = lengths[bbase + q];
        smax = (l > smax) ? l : smax;
    }

    unsigned target = 0;
    if (tid == 0) target = ld_acquire_gpu(&g_ggen[grp * 32]);

    float h0fin = 0.0f, h1fin = 0.0f;

    for (int s = 0; s <= smax; ++s) {
        const int p = s & 1;

        // ---- stage h0_after[s-1] | h1_after[s-2] into smem ----
        // (prior phase's hbuf reads are fenced by the barrier's syncthreads)
#pragma unroll
        for (int it = 0; it < 4; it++) {
            int i = tid + it * TPB;
            int r = i >> 7, c = (i & 127) << 2;
            float4 v0 = __ldcg((const float4*)&g_h0[p][bbase + r][c]);
            float4 v1 = __ldcg((const float4*)&g_h1[p][bbase + r][c]);
            *(float4*)(hbuf + (size_t)r * 1024 + c)       = v0;
            *(float4*)(hbuf + (size_t)r * 1024 + 512 + c) = v1;
        }
        // early pre0 load (hides DRAM/L2 latency under GEMM)
        float preval = (s < Tlen)
            ? __ldcs(&g_pre0[((size_t)s * Bsz + b_o) * Hdim + h_o]) : 0.0f;
        __syncthreads();

        unsigned long long acc2[4][4];
        float v[16];

        // ===== layer 0: h0_new = tanh(pre0 + h0 @ Whh0^T) =====
        if (s < Tlen) {
            phase_accum2<8, 512>(hbuf, Wa, tb, th, ks, acc2);
#pragma unroll
            for (int bi = 0; bi < 4; bi++)
#pragma unroll
                for (int hi = 0; hi < 4; hi++) {
                    float2 u = upk(acc2[bi][hi]);
                    v[bi * 4 + hi] = u.x + u.y;
                }
            fold16(v, ks);
            float sum = v[0] + preval;
            float hp0 = hbuf[(size_t)blo * 1024 + h_o];
            float hnew0 = (s < lenb) ? tanhf(sum) : hp0;
            g_h0[p ^ 1][b_o][h_o] = hnew0;
            h0fin = hnew0;
        }

        // ===== layer 1: h1_new = tanh([h0_new,h1] @ [Wih1|Whh1]^T + b1) =====
        if (s >= 1) {
            phase_accum2<16, 1024>(hbuf, Wb, tb, th, ks, acc2);
#pragma unroll
            for (int bi = 0; bi < 4; bi++)
#pragma unroll
                for (int hi = 0; hi < 4; hi++) {
                    float2 u = upk(acc2[bi][hi]);
                    v[bi * 4 + hi] = u.x + u.y;
                }
            fold16(v, ks);
            float sum = v[0] + bias1;
            float hp1 = hbuf[(size_t)blo * 1024 + 512 + h_o];
            float hnew1 = ((s - 1) < lenb) ? tanhf(sum) : hp1;
            g_h1[p ^ 1][b_o][h_o] = hnew1;
            h1fin = hnew1;
        }

        if (s < smax) group_barrier(grp, target);
    }

    // outputs: [ h1_final (64x512) | hidden (64x2x512: layer0, layer1) ]
    out[(size_t)b_o * Hdim + h_o] = h1fin;
    out[(size_t)Bsz * Hdim + (size_t)b_o * 2 * Hdim + h_o] = h0fin;
    out[(size_t)Bsz * Hdim + (size_t)b_o * 2 * Hdim + Hdim + h_o] = h1fin;
}

// ---------------------------------------------------------------------------
extern "C" void kernel_launch(void* const* d_in, const int* in_sizes, int n_in,
                              void* d_out, int out_size) {
    const int*   x       = (const int*)  d_in[0];
    const int*   lengths = (const int*)  d_in[1];
    const float* emb     = (const float*)d_in[2];
    const float* Wih     = (const float*)d_in[3];
    const float* Whh     = (const float*)d_in[4];
    const float* bih     = (const float*)d_in[5];
    const float* bhh     = (const float*)d_in[6];
    float* out = (float*)d_out;

    cudaFuncSetAttribute(rnn_seq_kernel,
                         cudaFuncAttributeMaxDynamicSharedMemorySize, SMEM_BYTES);

    zero_h_kernel<<<(2 * Bsz * Hdim + 255) / 256, 256>>>();

    dim3 grid_pre(Tlen, Hdim / 64);
    pre0_gemm_kernel<<<grid_pre, 256>>>(x, emb, Wih, bih, bhh);

    rnn_seq_kernel<<<NCTA, TPB, SMEM_BYTES>>>(Wih, Whh, bih, bhh, lengths, out);
}

// round 6
// speedup vs baseline: 2.0667x; 1.2336x over previous
#include <cuda_runtime.h>
#include <math.h>

#define Bsz   64
#define Tlen  512
#define Edim  512
#define Hdim  512
#define NCTA  128
#define TPB   128
// smem: Wa 32*512 + Wb 32*1024 + hbuf 8*1024 floats = 224 KB
#define SMEM_FLOATS (32*512 + 32*1024 + 8*1024)
#define SMEM_BYTES  (SMEM_FLOATS * 4)

__device__ float g_pre0[(size_t)Tlen * Bsz * Hdim];   // [t][b][h]
__device__ float g_h0[2][Bsz][Hdim];
__device__ float g_h1[2][Bsz][Hdim];
__device__ unsigned int g_cnt[8 * 32];   // per-group monotonic barrier counter

// ---------------------------------------------------------------------------
// primitives
// ---------------------------------------------------------------------------
__device__ __forceinline__ void atom_add_release_gpu(unsigned* p, unsigned v) {
    unsigned old;
    asm volatile("atom.add.release.gpu.u32 %0, [%1], %2;"
                 : "=r"(old) : "l"(p), "r"(v) : "memory");
}
__device__ __forceinline__ unsigned ld_acquire_gpu(const unsigned* p) {
    unsigned v;
    asm volatile("ld.acquire.gpu.u32 %0, [%1];" : "=r"(v) : "l"(p) : "memory");
    return v;
}
// packed fp32x2 FMA
__device__ __forceinline__ void F2(unsigned long long &d, unsigned long long a,
                                   unsigned long long b) {
    asm("fma.rn.f32x2 %0, %1, %2, %0;" : "+l"(d) : "l"(a), "l"(b));
}
__device__ __forceinline__ unsigned long long pk2(float x, float y) {
    unsigned long long p;
    asm("mov.b64 %0, {%1, %2};" : "=l"(p) : "f"(x), "f"(y));
    return p;
}
__device__ __forceinline__ float2 upk(unsigned long long v) {
    float2 r;
    asm("mov.b64 {%0, %1}, %2;" : "=f"(r.x), "=f"(r.y) : "l"(v));
    return r;
}

// ---------------------------------------------------------------------------
__global__ void zero_h_kernel() {
    int i = blockIdx.x * blockDim.x + threadIdx.x;
    if (i < 2 * Bsz * Hdim) {
        ((float*)g_h0)[i] = 0.0f;
        ((float*)g_h1)[i] = 0.0f;
    }
    if (i < 8 * 32) g_cnt[i] = 0;
}

// ---------------------------------------------------------------------------
// pre0[t][b][h] = emb[x[b,t]] . W_ih0[h] + b_ih0[h] + b_hh0[h]   (R4 version)
// ---------------------------------------------------------------------------
__global__ void __launch_bounds__(256) pre0_gemm_kernel(
    const int*   __restrict__ x,
    const float* __restrict__ emb,
    const float* __restrict__ Wih,
    const float* __restrict__ bih,
    const float* __restrict__ bhh)
{
    __shared__ unsigned long long As2[8][64];
    __shared__ unsigned long long Bs2[8][64];
    __shared__ int tok[64];

    const int tstep = blockIdx.x;
    const int ncol  = blockIdx.y * 64;
    const int tid   = threadIdx.x;

    if (tid < 64) tok[tid] = x[tid * Tlen + tstep];
    __syncthreads();

    const int ty = tid >> 4;
    const int tx = tid & 15;
    const int mm = tid & 63;
    const int kq = tid >> 6;
    const int pm = mm ^ (((mm >> 4) & 1) << 1);

    const int xa  = ((ty >> 2) & 1) << 1;
    const int xb  = ((tx >> 2) & 1) << 1;
    const int ca0 = (ty * 4) ^ xa, ca2 = (ty * 4 + 2) ^ xa;
    const int cb0 = (tx * 4) ^ xb, cb2 = (tx * 4 + 2) ^ xb;

    unsigned long long acc2[4][4];
#pragma unroll
    for (int i = 0; i < 4; i++)
#pragma unroll
        for (int j = 0; j < 4; j++) acc2[i][j] = 0ull;

    for (int kc = 0; kc < Edim; kc += 16) {
        {
            float4 v = *(const float4*)(emb + (size_t)tok[mm] * Edim + kc + kq * 4);
            As2[kq*2+0][pm] = pk2(v.x, v.y);
            As2[kq*2+1][pm] = pk2(v.z, v.w);
            float4 w = *(const float4*)(Wih + (size_t)(ncol + mm) * Edim + kc + kq * 4);
            Bs2[kq*2+0][pm] = pk2(w.x, w.y);
            Bs2[kq*2+1][pm] = pk2(w.z, w.w);
        }
        __syncthreads();
#pragma unroll
        for (int kk2 = 0; kk2 < 8; kk2++) {
            ulonglong2 a01 = *(const ulonglong2*)&As2[kk2][ca0];
            ulonglong2 a23 = *(const ulonglong2*)&As2[kk2][ca2];
            ulonglong2 b01 = *(const ulonglong2*)&Bs2[kk2][cb0];
            ulonglong2 b23 = *(const ulonglong2*)&Bs2[kk2][cb2];
            unsigned long long am[4] = {a01.x, a01.y, a23.x, a23.y};
            unsigned long long bn[4] = {b01.x, b01.y, b23.x, b23.y};
#pragma unroll
            for (int i = 0; i < 4; i++)
#pragma unroll
                for (int j = 0; j < 4; j++) F2(acc2[i][j], am[i], bn[j]);
        }
        __syncthreads();
    }

    const int nbase = ncol + tx * 4;
    float4 bias;
    bias.x = bih[nbase + 0] + bhh[nbase + 0];
    bias.y = bih[nbase + 1] + bhh[nbase + 1];
    bias.z = bih[nbase + 2] + bhh[nbase + 2];
    bias.w = bih[nbase + 3] + bhh[nbase + 3];
#pragma unroll
    for (int i = 0; i < 4; i++) {
        const int m = tstep * 64 + ty * 4 + i;
        float2 u0 = upk(acc2[i][0]), u1 = upk(acc2[i][1]);
        float2 u2 = upk(acc2[i][2]), u3 = upk(acc2[i][3]);
        float4 o;
        o.x = u0.x + u0.y + bias.x;  o.y = u1.x + u1.y + bias.y;
        o.z = u2.x + u2.y + bias.z;  o.w = u3.x + u3.y + bias.w;
        *(float4*)(g_pre0 + (size_t)m * Hdim + nbase) = o;
    }
}

// ---------------------------------------------------------------------------
// Per-group barrier: single monotonic counter (reset each launch by zero_h).
// ---------------------------------------------------------------------------
__device__ __forceinline__ void group_barrier(int grp, unsigned need) {
    __syncthreads();
    if (threadIdx.x == 0) {
        atom_add_release_gpu(&g_cnt[grp * 32], 1u);
        while (ld_acquire_gpu(&g_cnt[grp * 32]) < need) { }
    }
    __syncthreads();
}

// f32x2 GEMM phase: 4b x 8h outputs/thread, K-sliced 16 ways.
template<int JCOUNT, int WSTRIDE>
__device__ __forceinline__ void phase_accum2(
    const float* __restrict__ hbuf, const float* __restrict__ W,
    int tb, int th, int ks, unsigned long long acc[4][8])
{
#pragma unroll
    for (int bi = 0; bi < 4; bi++)
#pragma unroll
        for (int hi = 0; hi < 8; hi++) acc[bi][hi] = 0ull;

#pragma unroll 4
    for (int j = 0; j < JCOUNT; j++) {
        const int k = ((j * 16 + ks) << 2);
        ulonglong2 a[4], w[8];
#pragma unroll
        for (int q = 0; q < 4; q++)
            a[q] = *(const ulonglong2*)(hbuf + (size_t)(tb + q) * 1024 + k);
#pragma unroll
        for (int q = 0; q < 8; q++)
            w[q] = *(const ulonglong2*)(W + (size_t)(th + q) * WSTRIDE + k);
#pragma unroll
        for (int bi = 0; bi < 4; bi++)
#pragma unroll
            for (int hi = 0; hi < 8; hi++) {
                F2(acc[bi][hi], a[bi].x, w[hi].x);
                F2(acc[bi][hi], a[bi].y, w[hi].y);
            }
    }
}

// 32 partials/lane -> 2 full sums/lane across the 16-lane segment.
// Lane ks ends with outputs o = 2*ks (v[0]) and o = 2*ks+1 (v[1]),
// where o indexes the tile as (bi = o>>3, hi = o&7).
__device__ __forceinline__ void fold32to2(float v[32], int ks) {
    int cnt = 32;
#pragma unroll
    for (int m = 8; m >= 1; m >>= 1) {
        const bool hi = (ks & m) != 0;
        const int half = cnt >> 1;
#pragma unroll
        for (int j = 0; j < 16; j++) {
            if (j >= half) break;
            float send = hi ? v[j] : v[j + half];
            float recv = __shfl_xor_sync(0xffffffffu, send, m, 16);
            float keep = hi ? v[j + half] : v[j];
            v[j] = keep + recv;
        }
        cnt = half;
    }
}

// ---------------------------------------------------------------------------
// Persistent pipelined RNN. 128 CTAs = 8 groups of 16; 128 threads/CTA.
// Warp layout: lanes 0-15 (g=2w, tb=0|4), lanes 16-31 (g=2w+1, other tb),
// SAME th in both halves -> w-loads broadcast 2-way (smem BW halved on W).
// ---------------------------------------------------------------------------
__global__ void __launch_bounds__(TPB, 1) rnn_seq_kernel(
    const float* __restrict__ Wih,
    const float* __restrict__ Whh,
    const float* __restrict__ bih,
    const float* __restrict__ bhh,
    const int*   __restrict__ lengths,
    float*       __restrict__ out)
{
    extern __shared__ float smem_dyn[];
    float* Wa   = smem_dyn;                 // 32 x 512
    float* Wb   = smem_dyn + 32 * 512;      // 32 x 1024
    float* hbuf = Wb + 32 * 1024;           // 8 x 1024 staging

    const int cta   = blockIdx.x;
    const int grp   = cta >> 4;
    const int bbase = grp * 8;
    const int hbase = (cta & 15) * 32;
    const int tid   = threadIdx.x;

    // resident weight slices
    {
        const float4* src = (const float4*)(Whh + (size_t)hbase * Hdim);
        float4* dst = (float4*)Wa;
        for (int i = tid; i < 32 * Hdim / 4; i += TPB) dst[i] = src[i];

        const float4* s1 = (const float4*)(Wih + (size_t)Hdim * Edim + (size_t)hbase * Edim);
        const float4* s2 = (const float4*)(Whh + (size_t)Hdim * Hdim + (size_t)hbase * Hdim);
        for (int i = tid; i < 32 * 512 / 4; i += TPB) {
            int r = i >> 7, c = i & 127;
            ((float4*)(Wb + (size_t)r * 1024))[c]       = s1[i];
            ((float4*)(Wb + (size_t)r * 1024 + 512))[c] = s2[i];
        }
    }

    // compute mapping: g = tid>>4 (0..7); warp halves share th, differ in tb
    const int ks = tid & 15;
    const int g  = tid >> 4;
    const int tb = (g & 1) * 4;         // 4 batch rows
    const int th = (g >> 1) * 8;        // 8 h rows

    // epilogue ownership: lane ks owns outputs o=2ks, 2ks+1 (same b, h pair)
    const int blo = tb + (ks >> 2);              // local batch row
    const int hlo = th + 2 * (ks & 3);           // even local h row
    const int b_o = bbase + blo;
    const int h_o = hbase + hlo;                 // even -> float2-aligned
    const int lenb = lengths[b_o];
    float2 bias1;
    bias1.x = bih[Hdim + h_o] + bhh[Hdim + h_o];
    bias1.y = bih[Hdim + h_o + 1] + bhh[Hdim + h_o + 1];

    // group horizon
    int smax = 1;
#pragma unroll
    for (int q = 0; q < 8; q++) {
        int l = lengths[bbase + q];
        smax = (l > smax) ? l : smax;
    }

    float2 h0fin = make_float2(0.0f, 0.0f);
    float2 h1fin = make_float2(0.0f, 0.0f);

    for (int s = 0; s <= smax; ++s) {
        const int p = s & 1;

        // ---- stage h0_after[s-1] | h1_after[s-2] into smem ----
#pragma unroll
        for (int it = 0; it < 8; it++) {
            int i = tid + it * TPB;
            int r = i >> 7, c = (i & 127) << 2;
            float4 v0 = __ldcg((const float4*)&g_h0[p][bbase + r][c]);
            float4 v1 = __ldcg((const float4*)&g_h1[p][bbase + r][c]);
            *(float4*)(hbuf + (size_t)r * 1024 + c)       = v0;
            *(float4*)(hbuf + (size_t)r * 1024 + 512 + c) = v1;
        }
        // early pre0 load (hidden under GEMM)
        float2 preval = make_float2(0.0f, 0.0f);
        if (s < Tlen)
            preval = __ldcs((const float2*)&g_pre0[((size_t)s * Bsz + b_o) * Hdim + h_o]);
        __syncthreads();

        unsigned long long acc2[4][8];
        float v[32];

        // ===== layer 0: h0_new = tanh(pre0 + h0 @ Whh0^T) =====
        if (s < Tlen) {
            phase_accum2<8, 512>(hbuf, Wa, tb, th, ks, acc2);
#pragma unroll
            for (int bi = 0; bi < 4; bi++)
#pragma unroll
                for (int hi = 0; hi < 8; hi++) {
                    float2 u = upk(acc2[bi][hi]);
                    v[bi * 8 + hi] = u.x + u.y;
                }
            fold32to2(v, ks);
            float s0 = v[0] + preval.x;
            float s1 = v[1] + preval.y;
            float2 hp = *(const float2*)&hbuf[(size_t)blo * 1024 + h_o];
            float2 hn;
            hn.x = (s < lenb) ? tanhf(s0) : hp.x;
            hn.y = (s < lenb) ? tanhf(s1) : hp.y;
            *(float2*)&g_h0[p ^ 1][b_o][h_o] = hn;
            h0fin = hn;
        }

        // ===== layer 1: h1_new = tanh([h0_new,h1] @ [Wih1|Whh1]^T + b1) =====
        if (s >= 1) {
            phase_accum2<16, 1024>(hbuf, Wb, tb, th, ks, acc2);
#pragma unroll
            for (int bi = 0; bi < 4; bi++)
#pragma unroll
                for (int hi = 0; hi < 8; hi++) {
                    float2 u = upk(acc2[bi][hi]);
                    v[bi * 8 + hi] = u.x + u.y;
                }
            fold32to2(v, ks);
            float s0 = v[0] + bias1.x;
            float s1 = v[1] + bias1.y;
            float2 hp = *(const float2*)&hbuf[(size_t)blo * 1024 + 512 + h_o];
            float2 hn;
            hn.x = ((s - 1) < lenb) ? tanhf(s0) : hp.x;
            hn.y = ((s - 1) < lenb) ? tanhf(s1) : hp.y;
            if (s < Tlen) *(float2*)&g_h1[p ^ 1][b_o][h_o] = hn;
            h1fin = hn;
        }

        if (s < smax) group_barrier(grp, 16u * (unsigned)(s + 1));
    }

    // outputs: [ h1_final (64x512) | hidden (64x2x512: layer0, layer1) ]
    *(float2*)&out[(size_t)b_o * Hdim + h_o] = h1fin;
    *(float2*)&out[(size_t)Bsz * Hdim + (size_t)b_o * 2 * Hdim + h_o] = h0fin;
    *(float2*)&out[(size_t)Bsz * Hdim + (size_t)b_o * 2 * Hdim + Hdim + h_o] = h1fin;
}

// ---------------------------------------------------------------------------
extern "C" void kernel_launch(void* const* d_in, const int* in_sizes, int n_in,
                              void* d_out, int out_size) {
    const int*   x       = (const int*)  d_in[0];
    const int*   lengths = (const int*)  d_in[1];
    const float* emb     = (const float*)d_in[2];
    const float* Wih     = (const float*)d_in[3];
    const float* Whh     = (const float*)d_in[4];
    const float* bih     = (const float*)d_in[5];
    const float* bhh     = (const float*)d_in[6];
    float* out = (float*)d_out;

    cudaFuncSetAttribute(rnn_seq_kernel,
                         cudaFuncAttributeMaxDynamicSharedMemorySize, SMEM_BYTES);

    zero_h_kernel<<<(2 * Bsz * Hdim + 255) / 256, 256>>>();

    dim3 grid_pre(Tlen, Hdim / 64);
    pre0_gemm_kernel<<<grid_pre, 256>>>(x, emb, Wih, bih, bhh);

    rnn_seq_kernel<<<NCTA, TPB, SMEM_BYTES>>>(Wih, Whh, bih, bhh, lengths, out);
}